// round 6
// baseline (speedup 1.0000x reference)
#include <cuda_runtime.h>
#include <mma.h>
using namespace nvcuda;

// LessonGCN on GB300: out = GCNConv(relu(GCNConv(x)))
// (A_norm @ x) @ W1 reordering; layer 2 (OUT_DIM=1) fused into GEMM epilogue.
// R6: GEMM on tensor cores (wmma tf32 m16n16k8) with hi/lo split for fp32-class
//     accuracy (3 MMAs: ah*bh + ah*bl + al*bh). CSR aggregation unchanged.

#define N_NODES 100000
#define N_EDGES 1600000
#define IN_DIM  64
#define HID_DIM 128
#define SCAN_B  1024
#define NB_SCAN ((N_NODES + SCAN_B - 1) / SCAN_B)   // 98
#define GEMM_M  64

__device__ int   g_cnt[N_NODES];
__device__ int   g_off[N_NODES];
__device__ int   g_part[NB_SCAN];
__device__ int   g_csr_src[N_EDGES];
__device__ float g_dinv[N_NODES];
__device__ __align__(16) float g_y[(size_t)N_NODES * IN_DIM];
__device__ float g_h2[N_NODES];

__global__ void k_zero_cnt() {
    int i = blockIdx.x * blockDim.x + threadIdx.x;
    if (i < N_NODES) g_cnt[i] = 0;
}

__global__ void k_count(const int* __restrict__ dst) {
    int e = blockIdx.x * blockDim.x + threadIdx.x;
    if (e >= N_EDGES) return;
    unsigned d = (unsigned)dst[e];
    if (d < N_NODES) atomicAdd(&g_cnt[d], 1);
}

// Block-level exclusive scan of g_cnt -> g_off (block-local), totals -> g_part.
__global__ __launch_bounds__(SCAN_B) void k_scan1() {
    __shared__ int s[SCAN_B];
    int t = threadIdx.x;
    int idx = blockIdx.x * SCAN_B + t;
    int c = (idx < N_NODES) ? g_cnt[idx] : 0;
    s[t] = c;
    __syncthreads();
#pragma unroll
    for (int d = 1; d < SCAN_B; d <<= 1) {
        int v = (t >= d) ? s[t - d] : 0;
        __syncthreads();
        s[t] += v;
        __syncthreads();
    }
    if (idx < N_NODES) g_off[idx] = s[t] - c;  // exclusive within block
    if (t == SCAN_B - 1) g_part[blockIdx.x] = s[t];
}

// Finalize: every block redundantly scans the 98 partials in smem,
// adds the global offset, computes dinv. No separate scan2 launch.
__global__ __launch_bounds__(256) void k_scan_fin() {
    __shared__ int sp[128];
    int t = threadIdx.x;
    if (t < 128) {
        int c = (t < NB_SCAN) ? g_part[t] : 0;
        sp[t] = c;
    }
    __syncthreads();
#pragma unroll
    for (int d = 1; d < 128; d <<= 1) {
        int v = 0;
        if (t < 128 && t >= d) v = sp[t - d];
        __syncthreads();
        if (t < 128) sp[t] += v;
        __syncthreads();
    }
    int i = blockIdx.x * blockDim.x + t;
    if (i >= N_NODES) return;
    int blk = i / SCAN_B;
    int excl = (blk == 0) ? 0 : sp[blk - 1];
    g_off[i] += excl;
    g_dinv[i] = rsqrtf((float)g_cnt[i] + 1.0f);
}

// Scatter src ids into CSR; g_off[d] advances to segment end (= off + cnt).
__global__ void k_scatter(const int* __restrict__ src,
                          const int* __restrict__ dst) {
    int e = blockIdx.x * blockDim.x + threadIdx.x;
    if (e >= N_EDGES) return;
    unsigned s = (unsigned)src[e];
    unsigned d = (unsigned)dst[e];
    if (s >= N_NODES || d >= N_NODES) return;
    int p = atomicAdd(&g_off[d], 1);
    g_csr_src[p] = (int)s;
}

// Warp per node: gather-aggregate incoming x rows (float2/lane = 64 floats/warp),
// add self-loop term, write y once. Zero atomics.
__global__ __launch_bounds__(256) void k_agg_x(const float2* __restrict__ x2) {
    int w = (blockIdx.x * blockDim.x + threadIdx.x) >> 5;
    int lane = threadIdx.x & 31;
    if (w >= N_NODES) return;
    int n = w;
    int cnt = g_cnt[n];
    int base = g_off[n] - cnt;  // off was advanced to end by scatter
    float dn = g_dinv[n];

    float2 a0 = make_float2(0.f, 0.f);
    float2 a1 = make_float2(0.f, 0.f);
    int j = 0;
    for (; j + 2 <= cnt; j += 2) {
        int s0 = g_csr_src[base + j];
        int s1 = g_csr_src[base + j + 1];
        float n0 = g_dinv[s0] * dn;
        float n1 = g_dinv[s1] * dn;
        float2 v0 = x2[(size_t)s0 * 32 + lane];
        float2 v1 = x2[(size_t)s1 * 32 + lane];
        a0.x = fmaf(v0.x, n0, a0.x); a0.y = fmaf(v0.y, n0, a0.y);
        a1.x = fmaf(v1.x, n1, a1.x); a1.y = fmaf(v1.y, n1, a1.y);
    }
    if (j < cnt) {
        int s0 = g_csr_src[base + j];
        float n0 = g_dinv[s0] * dn;
        float2 v0 = x2[(size_t)s0 * 32 + lane];
        a0.x = fmaf(v0.x, n0, a0.x); a0.y = fmaf(v0.y, n0, a0.y);
    }
    float sl = dn * dn;  // self-loop: x[n] * dinv^2
    float2 vs = x2[(size_t)n * 32 + lane];
    a0.x = fmaf(vs.x, sl, a0.x + a1.x);
    a0.y = fmaf(vs.y, sl, a0.y + a1.y);
    reinterpret_cast<float2*>(g_y)[(size_t)n * 32 + lane] = a0;
}

// Tensor-core GEMM: block = 128 threads (4 warps), 64 nodes.
// C[64,128] = Y[64,64] @ W1[64,128] via tf32 wmma m16n16k8 with hi/lo split.
// Epilogue: h2[n] = relu(C[n,:]+b1).W2 ; out[n] = h2*dinv^2 + b2[0].
__global__ __launch_bounds__(128) void k_gemm_fused(
    const float* __restrict__ W1, const float* __restrict__ b1,
    const float* __restrict__ W2, const float* __restrict__ b2,
    float* __restrict__ out) {
    __shared__ __align__(16) float sY[GEMM_M * IN_DIM];      // 16KB
    __shared__ __align__(16) float sW1[IN_DIM * HID_DIM];    // 32KB (reused as C)
    __shared__ __align__(16) float sB1[HID_DIM];
    __shared__ __align__(16) float sW2[HID_DIM];

    int t = threadIdx.x;
    int node0 = blockIdx.x * GEMM_M;

    // Stage W1 (vectorized)
    {
        const float4* W14 = reinterpret_cast<const float4*>(W1);
        float4* sW14 = reinterpret_cast<float4*>(sW1);
        for (int i = t; i < IN_DIM * HID_DIM / 4; i += 128) sW14[i] = W14[i];
    }
    if (t < HID_DIM) { sB1[t] = b1[t]; sW2[t] = W2[t]; }

    // Stage y tile (zero-pad past N_NODES)
    {
        const float4* gy4 = reinterpret_cast<const float4*>(g_y) +
                            (size_t)node0 * (IN_DIM / 4);
        float4* sY4 = reinterpret_cast<float4*>(sY);
        int avail = N_NODES - node0;  // nodes available
        if (avail >= GEMM_M) {
            for (int i = t; i < GEMM_M * IN_DIM / 4; i += 128) sY4[i] = gy4[i];
        } else {
            for (int i = t; i < GEMM_M * IN_DIM / 4; i += 128) {
                int node = i / (IN_DIM / 4);
                sY4[i] = (node < avail) ? gy4[i] : make_float4(0.f, 0.f, 0.f, 0.f);
            }
        }
    }
    __syncthreads();

    int w = t >> 5;
    int m0 = w * 16;

    wmma::fragment<wmma::accumulator, 16, 16, 8, float> acc[8];
#pragma unroll
    for (int nt = 0; nt < 8; nt++) wmma::fill_fragment(acc[nt], 0.0f);

#pragma unroll
    for (int ks = 0; ks < 8; ks++) {
        wmma::fragment<wmma::matrix_a, 16, 16, 8, wmma::precision::tf32,
                       wmma::row_major> araw, ahi, alo;
        wmma::load_matrix_sync(araw, &sY[m0 * IN_DIM + ks * 8], IN_DIM);
#pragma unroll
        for (int i = 0; i < araw.num_elements; i++) {
            float f = araw.x[i];
            float h = wmma::__float_to_tf32(f);
            ahi.x[i] = h;
            alo.x[i] = wmma::__float_to_tf32(f - h);
        }
#pragma unroll
        for (int nt = 0; nt < 8; nt++) {
            wmma::fragment<wmma::matrix_b, 16, 16, 8, wmma::precision::tf32,
                           wmma::row_major> braw, bhi, blo;
            wmma::load_matrix_sync(braw, &sW1[(ks * 8) * HID_DIM + nt * 16], HID_DIM);
#pragma unroll
            for (int i = 0; i < braw.num_elements; i++) {
                float f = braw.x[i];
                float h = wmma::__float_to_tf32(f);
                bhi.x[i] = h;
                blo.x[i] = wmma::__float_to_tf32(f - h);
            }
            wmma::mma_sync(acc[nt], ahi, bhi, acc[nt]);
            wmma::mma_sync(acc[nt], ahi, blo, acc[nt]);
            wmma::mma_sync(acc[nt], alo, bhi, acc[nt]);
        }
    }
    __syncthreads();  // everyone done reading sW1 -> reuse as C

    float* sC = sW1;
#pragma unroll
    for (int nt = 0; nt < 8; nt++)
        wmma::store_matrix_sync(&sC[m0 * HID_DIM + nt * 16], acc[nt], HID_DIM,
                                wmma::mem_row_major);
    __syncthreads();

    // Epilogue: thread t handles node (t>>1), j-half (t&1)*64; pair-reduce.
    int local = t >> 1;
    int n = node0 + local;
    int j0 = (t & 1) * 64;
    const float* crow = &sC[local * HID_DIM];
    float h2p = 0.0f;
#pragma unroll 8
    for (int jj = 0; jj < 64; jj++) {
        int j = j0 + ((jj + 2 * local) & 63);  // stagger to avoid bank conflicts
        h2p = fmaf(fmaxf(crow[j] + sB1[j], 0.0f), sW2[j], h2p);
    }
    float other = __shfl_xor_sync(0xFFFFFFFFu, h2p, 1);
    if ((t & 1) == 0 && n < N_NODES) {
        float h2 = h2p + other;
        g_h2[n] = h2;
        float dinv = g_dinv[n];
        out[n] = fmaf(h2, dinv * dinv, b2[0]);
    }
}

// Warp per node: gather h2[src]*dinv[src], warp-reduce, lane0 accumulates into out.
__global__ __launch_bounds__(256) void k_agg_h2(float* __restrict__ out) {
    int w = (blockIdx.x * blockDim.x + threadIdx.x) >> 5;
    int lane = threadIdx.x & 31;
    if (w >= N_NODES) return;
    int n = w;
    int cnt = g_cnt[n];
    int base = g_off[n] - cnt;

    float acc = 0.0f;
    for (int j = lane; j < cnt; j += 32) {
        int s = g_csr_src[base + j];
        acc += g_h2[s] * g_dinv[s];
    }
#pragma unroll
    for (int o = 16; o > 0; o >>= 1)
        acc += __shfl_down_sync(0xFFFFFFFFu, acc, o);
    if (lane == 0)
        out[n] += acc * g_dinv[n];
}

extern "C" void kernel_launch(void* const* d_in, const int* in_sizes, int n_in,
                              void* d_out, int out_size) {
    const float* x   = (const float*)d_in[0];
    const int*   ei  = (const int*)d_in[1];   // int32 (JAX x64 disabled)
    const float* W1  = (const float*)d_in[2];
    const float* b1  = (const float*)d_in[3];
    const float* W2  = (const float*)d_in[4];
    const float* b2  = (const float*)d_in[5];
    float* out       = (float*)d_out;

    const int* src = ei;
    const int* dst = ei + N_EDGES;

    const int T = 256;
    k_zero_cnt<<<(N_NODES + T - 1) / T, T>>>();
    k_count<<<(N_EDGES + T - 1) / T, T>>>(dst);
    k_scan1<<<NB_SCAN, SCAN_B>>>();
    k_scan_fin<<<(N_NODES + T - 1) / T, T>>>();
    k_scatter<<<(N_EDGES + T - 1) / T, T>>>(src, dst);
    k_agg_x<<<(N_NODES * 32 + T - 1) / T, T>>>((const float2*)x);
    k_gemm_fused<<<(N_NODES + GEMM_M - 1) / GEMM_M, 128>>>(W1, b1, W2, b2, out);
    k_agg_h2<<<(N_NODES * 32 + T - 1) / T, T>>>(out);
}

// round 7
// speedup vs baseline: 1.1438x; 1.1438x over previous
#include <cuda_runtime.h>

// LessonGCN on GB300: out = GCNConv(relu(GCNConv(x)))
// (A_norm @ x) @ W1 reordering; layer 2 (OUT_DIM=1) fused into GEMM epilogue.
// R7: register-blocked f32x2 GEMM (8 nodes x 8 cols per thread, transposed
//     y-tile in smem), shfl-broadcast prefetch in agg_x. CSR build unchanged.

#define N_NODES 100000
#define N_EDGES 1600000
#define IN_DIM  64
#define HID_DIM 128
#define SCAN_B  1024
#define NB_SCAN ((N_NODES + SCAN_B - 1) / SCAN_B)   // 98
#define GM      128                                  // nodes per gemm block
#define GPAD    132                                  // sYt row stride (floats)
#define GEMM_SMEM ((IN_DIM * GPAD + IN_DIM * HID_DIM) * 4)  // 66560 bytes

__device__ int   g_cnt[N_NODES];
__device__ int   g_off[N_NODES];
__device__ int   g_part[NB_SCAN];
__device__ int   g_csr_src[N_EDGES];
__device__ float g_dinv[N_NODES];
__device__ __align__(16) float g_y[(size_t)N_NODES * IN_DIM];
__device__ float g_h2[N_NODES];

__global__ void k_zero_cnt() {
    int i = blockIdx.x * blockDim.x + threadIdx.x;
    if (i < N_NODES) g_cnt[i] = 0;
}

__global__ void k_count(const int* __restrict__ dst) {
    int e = blockIdx.x * blockDim.x + threadIdx.x;
    if (e >= N_EDGES) return;
    unsigned d = (unsigned)dst[e];
    if (d < N_NODES) atomicAdd(&g_cnt[d], 1);
}

// Block-level exclusive scan of g_cnt -> g_off (block-local), totals -> g_part.
__global__ __launch_bounds__(SCAN_B) void k_scan1() {
    __shared__ int s[SCAN_B];
    int t = threadIdx.x;
    int idx = blockIdx.x * SCAN_B + t;
    int c = (idx < N_NODES) ? g_cnt[idx] : 0;
    s[t] = c;
    __syncthreads();
#pragma unroll
    for (int d = 1; d < SCAN_B; d <<= 1) {
        int v = (t >= d) ? s[t - d] : 0;
        __syncthreads();
        s[t] += v;
        __syncthreads();
    }
    if (idx < N_NODES) g_off[idx] = s[t] - c;
    if (t == SCAN_B - 1) g_part[blockIdx.x] = s[t];
}

// Finalize: every block redundantly scans the 98 partials; adds global offset;
// computes dinv.
__global__ __launch_bounds__(256) void k_scan_fin() {
    __shared__ int sp[128];
    int t = threadIdx.x;
    if (t < 128) {
        int c = (t < NB_SCAN) ? g_part[t] : 0;
        sp[t] = c;
    }
    __syncthreads();
#pragma unroll
    for (int d = 1; d < 128; d <<= 1) {
        int v = 0;
        if (t < 128 && t >= d) v = sp[t - d];
        __syncthreads();
        if (t < 128) sp[t] += v;
        __syncthreads();
    }
    int i = blockIdx.x * blockDim.x + t;
    if (i >= N_NODES) return;
    int blk = i / SCAN_B;
    int excl = (blk == 0) ? 0 : sp[blk - 1];
    g_off[i] += excl;
    g_dinv[i] = rsqrtf((float)g_cnt[i] + 1.0f);
}

// Scatter src ids into CSR; g_off[d] advances to segment end (= off + cnt).
__global__ void k_scatter(const int* __restrict__ src,
                          const int* __restrict__ dst) {
    int e = blockIdx.x * blockDim.x + threadIdx.x;
    if (e >= N_EDGES) return;
    unsigned s = (unsigned)src[e];
    unsigned d = (unsigned)dst[e];
    if (s >= N_NODES || d >= N_NODES) return;
    int p = atomicAdd(&g_off[d], 1);
    g_csr_src[p] = (int)s;
}

// Warp per node. Lanes cooperatively prefetch 32 (src,dinv) pairs, broadcast
// via shfl; gather x rows with 4-edge unroll for MLP. Zero atomics.
__global__ __launch_bounds__(256) void k_agg_x(const float2* __restrict__ x2) {
    int w = (blockIdx.x * blockDim.x + threadIdx.x) >> 5;
    int lane = threadIdx.x & 31;
    if (w >= N_NODES) return;
    int n = w;
    int cnt = g_cnt[n];
    int base = g_off[n] - cnt;
    float dn = g_dinv[n];

    float2 acc = make_float2(0.f, 0.f);
    for (int j0 = 0; j0 < cnt; j0 += 32) {
        int rem = cnt - j0;
        int id = 0; float dv = 0.f;
        if (lane < rem) { id = g_csr_src[base + j0 + lane]; dv = g_dinv[id]; }
        int m = rem < 32 ? rem : 32;
        int jj = 0;
        for (; jj + 4 <= m; jj += 4) {
            int s0 = __shfl_sync(0xFFFFFFFFu, id, jj);
            int s1 = __shfl_sync(0xFFFFFFFFu, id, jj + 1);
            int s2 = __shfl_sync(0xFFFFFFFFu, id, jj + 2);
            int s3 = __shfl_sync(0xFFFFFFFFu, id, jj + 3);
            float n0 = __shfl_sync(0xFFFFFFFFu, dv, jj) * dn;
            float n1 = __shfl_sync(0xFFFFFFFFu, dv, jj + 1) * dn;
            float n2 = __shfl_sync(0xFFFFFFFFu, dv, jj + 2) * dn;
            float n3 = __shfl_sync(0xFFFFFFFFu, dv, jj + 3) * dn;
            float2 v0 = x2[(size_t)s0 * 32 + lane];
            float2 v1 = x2[(size_t)s1 * 32 + lane];
            float2 v2 = x2[(size_t)s2 * 32 + lane];
            float2 v3 = x2[(size_t)s3 * 32 + lane];
            acc.x = fmaf(v0.x, n0, acc.x); acc.y = fmaf(v0.y, n0, acc.y);
            acc.x = fmaf(v1.x, n1, acc.x); acc.y = fmaf(v1.y, n1, acc.y);
            acc.x = fmaf(v2.x, n2, acc.x); acc.y = fmaf(v2.y, n2, acc.y);
            acc.x = fmaf(v3.x, n3, acc.x); acc.y = fmaf(v3.y, n3, acc.y);
        }
        for (; jj < m; jj++) {
            int s0 = __shfl_sync(0xFFFFFFFFu, id, jj);
            float n0 = __shfl_sync(0xFFFFFFFFu, dv, jj) * dn;
            float2 v0 = x2[(size_t)s0 * 32 + lane];
            acc.x = fmaf(v0.x, n0, acc.x); acc.y = fmaf(v0.y, n0, acc.y);
        }
    }
    float sl = dn * dn;  // self-loop: x[n] * dinv^2
    float2 vs = x2[(size_t)n * 32 + lane];
    acc.x = fmaf(vs.x, sl, acc.x);
    acc.y = fmaf(vs.y, sl, acc.y);
    reinterpret_cast<float2*>(g_y)[(size_t)n * 32 + lane] = acc;
}

// Register-blocked GEMM + fused epilogue.
// Block: 256 threads = 16 tx (j-slices of 8) x 16 ty (node-slices of 8), 128 nodes.
// sYt: transposed y tile [64][GPAD]; sW1: [64][128] row-major.
// Thread: acc[8 nodes][8 j] as 32 packed f32x2; per k: 2 LDS.128 (y) +
// 2 LDS.128 (W pairs) + 8 dup-movs + 32 fma.rn.f32x2.
__global__ __launch_bounds__(256) void k_gemm_fused(
    const float* __restrict__ W1, const float* __restrict__ b1,
    const float* __restrict__ W2, const float* __restrict__ b2,
    float* __restrict__ out) {
    extern __shared__ float smem_dyn[];
    float* sYt = smem_dyn;                    // [IN_DIM][GPAD]
    float* sW1 = smem_dyn + IN_DIM * GPAD;    // [IN_DIM][HID_DIM]

    int t = threadIdx.x;
    int node0 = blockIdx.x * GM;

    // Stage W1 (coalesced float4)
    {
        const float4* W14 = reinterpret_cast<const float4*>(W1);
        float4* sW14 = reinterpret_cast<float4*>(sW1);
        for (int i = t; i < IN_DIM * HID_DIM / 4; i += 256) sW14[i] = W14[i];
    }
    // Stage y transposed: lane i -> node ln = i&127, k-chunk i>>7.
    // Stores conflict-free (ln spans banks); global reads are 16B scattered
    // but L2-resident.
    for (int i = t; i < GM * (IN_DIM / 4); i += 256) {
        int ln = i & (GM - 1);
        int kc = i >> 7;            // 0..15
        int n = node0 + ln;
        float4 v = (n < N_NODES)
                       ? reinterpret_cast<const float4*>(g_y)[(size_t)n * 16 + kc]
                       : make_float4(0.f, 0.f, 0.f, 0.f);
        int k = kc * 4;
        sYt[(k + 0) * GPAD + ln] = v.x;
        sYt[(k + 1) * GPAD + ln] = v.y;
        sYt[(k + 2) * GPAD + ln] = v.z;
        sYt[(k + 3) * GPAD + ln] = v.w;
    }
    __syncthreads();

    int tx = t & 15;
    int ty = t >> 4;
    int jb = tx * 8;
    int nb = ty * 8;

    unsigned long long acc[8][4];
#pragma unroll
    for (int a = 0; a < 8; a++)
#pragma unroll
        for (int p = 0; p < 4; p++) acc[a][p] = 0ull;

#pragma unroll 8
    for (int k = 0; k < IN_DIM; k++) {
        const float4* yp = reinterpret_cast<const float4*>(&sYt[k * GPAD + nb]);
        float4 ya = yp[0], yb = yp[1];
        float yv[8] = {ya.x, ya.y, ya.z, ya.w, yb.x, yb.y, yb.z, yb.w};
        const ulonglong2* wp = reinterpret_cast<const ulonglong2*>(&sW1[k * HID_DIM + jb]);
        ulonglong2 w0 = wp[0], w1 = wp[1];
        unsigned long long wj[4] = {w0.x, w0.y, w1.x, w1.y};
#pragma unroll
        for (int a = 0; a < 8; a++) {
            unsigned long long yd;
            asm("mov.b64 %0, {%1, %1};" : "=l"(yd) : "f"(yv[a]));
#pragma unroll
            for (int p = 0; p < 4; p++)
                asm("fma.rn.f32x2 %0, %1, %2, %0;"
                    : "+l"(acc[a][p]) : "l"(yd), "l"(wj[p]));
        }
    }

    // Epilogue: per-node partial h2 over this thread's 8 j's, then reduce
    // across the 16 tx lanes (xor masks 1..8 stay within the ty half-warp).
    float4 b1a = *reinterpret_cast<const float4*>(b1 + jb);
    float4 b1b = *reinterpret_cast<const float4*>(b1 + jb + 4);
    float4 w2a = *reinterpret_cast<const float4*>(W2 + jb);
    float4 w2b = *reinterpret_cast<const float4*>(W2 + jb + 4);
    float b1r[8] = {b1a.x, b1a.y, b1a.z, b1a.w, b1b.x, b1b.y, b1b.z, b1b.w};
    float w2r[8] = {w2a.x, w2a.y, w2a.z, w2a.w, w2b.x, w2b.y, w2b.z, w2b.w};

    float part[8];
#pragma unroll
    for (int a = 0; a < 8; a++) {
        float s = 0.f;
#pragma unroll
        for (int p = 0; p < 4; p++) {
            float lo, hi;
            asm("mov.b64 {%0, %1}, %2;" : "=f"(lo), "=f"(hi) : "l"(acc[a][p]));
            s = fmaf(fmaxf(lo + b1r[2 * p], 0.f), w2r[2 * p], s);
            s = fmaf(fmaxf(hi + b1r[2 * p + 1], 0.f), w2r[2 * p + 1], s);
        }
        part[a] = s;
    }
#pragma unroll
    for (int m = 1; m < 16; m <<= 1)
#pragma unroll
        for (int a = 0; a < 8; a++)
            part[a] += __shfl_xor_sync(0xFFFFFFFFu, part[a], m);

    if (tx == 0) {
        float bias2 = b2[0];
#pragma unroll
        for (int a = 0; a < 8; a++) {
            int n = node0 + nb + a;
            if (n < N_NODES) {
                float dinv = g_dinv[n];
                g_h2[n] = part[a];
                out[n] = fmaf(part[a], dinv * dinv, bias2);
            }
        }
    }
}

// Warp per node: gather h2[src]*dinv[src], warp-reduce, lane0 accumulates.
__global__ __launch_bounds__(256) void k_agg_h2(float* __restrict__ out) {
    int w = (blockIdx.x * blockDim.x + threadIdx.x) >> 5;
    int lane = threadIdx.x & 31;
    if (w >= N_NODES) return;
    int n = w;
    int cnt = g_cnt[n];
    int base = g_off[n] - cnt;

    float acc = 0.0f;
    for (int j = lane; j < cnt; j += 32) {
        int s = g_csr_src[base + j];
        acc += g_h2[s] * g_dinv[s];
    }
#pragma unroll
    for (int o = 16; o > 0; o >>= 1)
        acc += __shfl_down_sync(0xFFFFFFFFu, acc, o);
    if (lane == 0)
        out[n] += acc * g_dinv[n];
}

extern "C" void kernel_launch(void* const* d_in, const int* in_sizes, int n_in,
                              void* d_out, int out_size) {
    const float* x   = (const float*)d_in[0];
    const int*   ei  = (const int*)d_in[1];   // int32 (JAX x64 disabled)
    const float* W1  = (const float*)d_in[2];
    const float* b1  = (const float*)d_in[3];
    const float* W2  = (const float*)d_in[4];
    const float* b2  = (const float*)d_in[5];
    float* out       = (float*)d_out;

    const int* src = ei;
    const int* dst = ei + N_EDGES;

    cudaFuncSetAttribute(k_gemm_fused,
                         cudaFuncAttributeMaxDynamicSharedMemorySize, GEMM_SMEM);

    const int T = 256;
    k_zero_cnt<<<(N_NODES + T - 1) / T, T>>>();
    k_count<<<(N_EDGES + T - 1) / T, T>>>(dst);
    k_scan1<<<NB_SCAN, SCAN_B>>>();
    k_scan_fin<<<(N_NODES + T - 1) / T, T>>>();
    k_scatter<<<(N_EDGES + T - 1) / T, T>>>(src, dst);
    k_agg_x<<<(N_NODES * 32 + T - 1) / T, T>>>((const float2*)x);
    k_gemm_fused<<<(N_NODES + GM - 1) / GM, 256, GEMM_SMEM>>>(W1, b1, W2, b2, out);
    k_agg_h2<<<(N_NODES * 32 + T - 1) / T, T>>>(out);
}